// round 13
// baseline (speedup 1.0000x reference)
#include <cuda_runtime.h>
#include <cuda_fp16.h>
#include <mma.h>
#include <cstdint>

// ---------------------------------------------------------------------------
// 3-layer GCN: h = D^-1/2 (A+I) D^-1/2 (X W) + b, relu after layers 1,2.
//   1. CSR-by-dst: (init+detect) + hist(ranks) + fused lookback scan +
//      ATOMIC-FREE scatter (pos = off[d] + rank[e]).
//   2. WMMA (HMMA) fp16 GEMM, fp32 accumulate; epilogue scales by dinv[row],
//      stores fp16 into the gather buffer. Layer-1 GEMM forked onto a second
//      stream so it overlaps the scatter during graph replay.
//   3. Warp-per-node pull aggregation (fp16 gathers, fp32 accumulate).
// ---------------------------------------------------------------------------

#define MAXN 50000
#define MAXE 800000
#define SCAN_B 1024
#define SCAN_GRID ((MAXN + SCAN_B - 1) / SCAN_B)   // 49

__device__ __half g_hh[(size_t)MAXN * 128];  // GEMM output (row-scaled, fp16)
__device__ float  g_t[(size_t)MAXN * 128];   // aggregation output / next input
__device__ float  g_dinv[MAXN];
__device__ int    g_cnt[MAXN];
__device__ int    g_off[MAXN + 1];
__device__ int    g_rank[MAXE];              // rank of edge within its dst
__device__ int    g_srcs[MAXE];
__device__ int    g_bflag[SCAN_GRID];        // lookback: block_sum+1, 0=unset
__device__ int    g_is64;

// ---------------------------------------------------------------------------
// init + edge dtype detection fused (block 0 detects, all blocks zero cnt).
// ---------------------------------------------------------------------------
__global__ void init_detect_kernel(const void* edges, int E, int n) {
    int i = blockIdx.x * blockDim.x + threadIdx.x;
    if (i < n) g_cnt[i] = 0;
    if (i < SCAN_GRID) g_bflag[i] = 0;
    if (blockIdx.x == 0) {
        __shared__ int nz;
        if (threadIdx.x == 0) nz = 0;
        __syncthreads();
        const int* w = (const int*)edges;
        int cnt = 0;
        for (int k = threadIdx.x; k < 2048; k += blockDim.x) {
            int idx = 2 * k + 1;
            if (idx < 2 * E && w[idx] != 0) cnt++;
        }
        atomicAdd(&nz, cnt);
        __syncthreads();
        if (threadIdx.x == 0) g_is64 = (nz == 0) ? 1 : 0;
    }
}

__device__ __forceinline__ int edge_val(const void* p, long long idx) {
    if (g_is64) return (int)((const long long*)p)[idx];
    return ((const int*)p)[idx];
}

// 4 edges per thread; atomicAdd result IS the edge's rank within its dst.
__global__ void hist_kernel(const void* edges, int E) {
    int base = blockIdx.x * (blockDim.x * 4) + threadIdx.x;
    int d[4], e_[4];
#pragma unroll
    for (int k = 0; k < 4; k++) {
        e_[k] = base + k * blockDim.x;
        d[k] = (e_[k] < E) ? edge_val(edges, (long long)E + e_[k]) : -1;
    }
#pragma unroll
    for (int k = 0; k < 4; k++)
        if (d[k] >= 0) g_rank[e_[k]] = atomicAdd(&g_cnt[d[k]], 1);
}

// ---------------------------------------------------------------------------
// Single-kernel scan with decoupled lookback (49 co-resident blocks).
// ---------------------------------------------------------------------------
__global__ __launch_bounds__(SCAN_B) void scan_fused_kernel(int n, int E) {
    __shared__ int wsum[32];
    __shared__ int sums[SCAN_GRID];
    __shared__ int base_sh;
    const int b = blockIdx.x;
    int gid = b * SCAN_B + threadIdx.x;
    int lane = threadIdx.x & 31;
    int wid = threadIdx.x >> 5;

    int c = (gid < n) ? g_cnt[gid] : 0;
    if (gid < n) g_dinv[gid] = rsqrtf((float)(c + 1));

    int v = c;
#pragma unroll
    for (int o = 1; o < 32; o <<= 1) {
        int u = __shfl_up_sync(0xffffffffu, v, o);
        if (lane >= o) v += u;
    }
    if (lane == 31) wsum[wid] = v;
    __syncthreads();
    if (wid == 0) {
        int w = (lane < SCAN_B / 32) ? wsum[lane] : 0;
#pragma unroll
        for (int o = 1; o < 32; o <<= 1) {
            int u = __shfl_up_sync(0xffffffffu, w, o);
            if (lane >= o) w += u;
        }
        wsum[lane] = w;
    }
    __syncthreads();
    int wbase = (wid == 0) ? 0 : wsum[wid - 1];
    int excl = wbase + v - c;

    if (threadIdx.x == SCAN_B - 1)
        atomicExch(&g_bflag[b], wbase + v + 1);

    if (threadIdx.x < SCAN_GRID) {
        volatile int* f = g_bflag;
        int val;
        do { val = f[threadIdx.x]; } while (val == 0);
        sums[threadIdx.x] = val - 1;
    }
    __syncthreads();
    if (threadIdx.x == 0) {
        int base = 0;
        for (int j = 0; j < b; j++) base += sums[j];
        base_sh = base;
    }
    __syncthreads();

    if (gid < n) g_off[gid] = excl + base_sh;
    if (b == SCAN_GRID - 1 && threadIdx.x == SCAN_B - 1) g_off[n] = E;
}

// Atomic-free scatter: pos = g_off[d] + rank[e]. 4 edges/thread, MLP=4.
__global__ void scatter_kernel(const void* edges, int E) {
    int base = blockIdx.x * (blockDim.x * 4) + threadIdx.x;
    int d[4], s[4], r[4], e_[4];
#pragma unroll
    for (int k = 0; k < 4; k++) {
        e_[k] = base + k * blockDim.x;
        if (e_[k] < E) {
            d[k] = edge_val(edges, (long long)E + e_[k]);
            s[k] = edge_val(edges, e_[k]);
            r[k] = g_rank[e_[k]];
        } else d[k] = -1;
    }
    int off[4];
#pragma unroll
    for (int k = 0; k < 4; k++)
        off[k] = (d[k] >= 0) ? g_off[d[k]] : 0;
#pragma unroll
    for (int k = 0; k < 4; k++)
        if (d[k] >= 0) g_srcs[off[k] + r[k]] = s[k];
}

// ---------------------------------------------------------------------------
// WMMA fp16 GEMM: Ch[M,N] = fp16( (A[M,128] @ W[128,N]) * dinv[row] )
// ---------------------------------------------------------------------------
template <int N>
__global__ __launch_bounds__(256) void gemm_wmma_kernel(
    const float* __restrict__ A, const float* __restrict__ W,
    __half* __restrict__ Ch, int M)
{
    using namespace nvcuda;
    constexpr int K = 128, BM = 128;
    constexpr int LDA = K + 16;
    constexpr int LDW = N + 16;
    constexpr int LDS_ = 24;
    constexpr int WMF = 2;
    constexpr int WNF = N / 32;

    extern __shared__ __align__(32) char smem[];
    __half* Wh = (__half*)smem;
    __half* Ah = (__half*)(smem + (size_t)K * LDW * 2);
    float* stage = (float*)(smem + (size_t)K * LDW * 2 + (size_t)BM * LDA * 2);

    const int tid = threadIdx.x;
    const int wid = tid >> 5;
    const int lane = tid & 31;
    const int warp_m = wid & 3;
    const int warp_n = wid >> 2;
    float* st = stage + wid * 16 * LDS_;

    for (int g = tid; g < K * N / 4; g += 256) {
        int k  = g / (N / 4);
        int c4 = (g % (N / 4)) * 4;
        float4 v = *(const float4*)&W[(size_t)k * N + c4];
        __half2 h01 = __floats2half2_rn(v.x, v.y);
        __half2 h23 = __floats2half2_rn(v.z, v.w);
        uint2 u = make_uint2(*(uint32_t*)&h01, *(uint32_t*)&h23);
        *(uint2*)&Wh[(size_t)k * LDW + c4] = u;
    }

    const int n_tiles = (M + BM - 1) / BM;
    for (int tile = blockIdx.x; tile < n_tiles; tile += gridDim.x) {
        const int brow = tile * BM;

        for (int g = tid; g < BM * K / 4; g += 256) {
            int r  = g >> 5;
            int c4 = (g & 31) * 4;
            float4 v = make_float4(0.f, 0.f, 0.f, 0.f);
            if (brow + r < M)
                v = *(const float4*)&A[(size_t)(brow + r) * K + c4];
            __half2 h01 = __floats2half2_rn(v.x, v.y);
            __half2 h23 = __floats2half2_rn(v.z, v.w);
            uint2 u = make_uint2(*(uint32_t*)&h01, *(uint32_t*)&h23);
            *(uint2*)&Ah[(size_t)r * LDA + c4] = u;
        }
        __syncthreads();

        wmma::fragment<wmma::accumulator, 16, 16, 16, float> cf[WMF][WNF];
#pragma unroll
        for (int i = 0; i < WMF; i++)
#pragma unroll
            for (int j = 0; j < WNF; j++)
                wmma::fill_fragment(cf[i][j], 0.f);

#pragma unroll
        for (int k = 0; k < K; k += 16) {
            wmma::fragment<wmma::matrix_a, 16, 16, 16, __half, wmma::row_major> af[WMF];
#pragma unroll
            for (int i = 0; i < WMF; i++)
                wmma::load_matrix_sync(af[i],
                    &Ah[(size_t)(warp_m * 32 + i * 16) * LDA + k], LDA);
#pragma unroll
            for (int j = 0; j < WNF; j++) {
                wmma::fragment<wmma::matrix_b, 16, 16, 16, __half, wmma::row_major> bf;
                wmma::load_matrix_sync(bf,
                    &Wh[(size_t)k * LDW + warp_n * WNF * 16 + j * 16], LDW);
#pragma unroll
                for (int i = 0; i < WMF; i++)
                    wmma::mma_sync(cf[i][j], af[i], bf, cf[i][j]);
            }
        }

#pragma unroll
        for (int i = 0; i < WMF; i++) {
#pragma unroll
            for (int j = 0; j < WNF; j++) {
                wmma::store_matrix_sync(st, cf[i][j], LDS_, wmma::mem_row_major);
                __syncwarp();
                int rloc = lane >> 1;
                int cg = (lane & 1) * 8;
                int r = brow + warp_m * 32 + i * 16 + rloc;
                if (r < M) {
                    float s = g_dinv[r];
                    float4 va = *(float4*)&st[rloc * LDS_ + cg + 0];
                    float4 vb = *(float4*)&st[rloc * LDS_ + cg + 4];
                    __align__(16) __half2 hv[4];
                    hv[0] = __floats2half2_rn(va.x * s, va.y * s);
                    hv[1] = __floats2half2_rn(va.z * s, va.w * s);
                    hv[2] = __floats2half2_rn(vb.x * s, vb.y * s);
                    hv[3] = __floats2half2_rn(vb.z * s, vb.w * s);
                    __half* dst = &Ch[(size_t)r * N + warp_n * WNF * 16 + j * 16 + cg];
                    *(uint4*)dst = *(uint4*)hv;
                }
                __syncwarp();
            }
        }
        __syncthreads();
    }
}

// ---------------------------------------------------------------------------
// Warp-per-node aggregation: fp16 gathers, fp32 accumulate.
// ---------------------------------------------------------------------------
__device__ __forceinline__ float4 gather4h(const __half* g, int row, int lane) {
    uint2 u = *(const uint2*)(g + (size_t)row * 128 + lane * 4);
    __half2 h0 = *(__half2*)&u.x;
    __half2 h1 = *(__half2*)&u.y;
    float2 f0 = __half22float2(h0);
    float2 f1 = __half22float2(h1);
    return make_float4(f0.x, f0.y, f1.x, f1.y);
}

template <bool RELU>
__global__ void aggregate128_kernel(const __half* __restrict__ g,
                                    const float* __restrict__ bias,
                                    float* __restrict__ out, int n)
{
    int warp = (blockIdx.x * blockDim.x + threadIdx.x) >> 5;
    if (warp >= n) return;
    int lane = threadIdx.x & 31;

    float4 acc = gather4h(g, warp, lane);   // self-loop term
    int e = g_off[warp];
    int end = g_off[warp + 1];
    while (e < end) {
        int m = min(32, end - e);
        int s = (lane < m) ? g_srcs[e + lane] : 0;
#pragma unroll 4
        for (int j = 0; j < m; j++) {
            int sj = __shfl_sync(0xffffffffu, s, j);
            float4 v = gather4h(g, sj, lane);
            acc.x += v.x; acc.y += v.y; acc.z += v.z; acc.w += v.w;
        }
        e += m;
    }
    float sc = g_dinv[warp];
    float4 bv = ((const float4*)bias)[lane];
    float4 o;
    o.x = acc.x * sc + bv.x;
    o.y = acc.y * sc + bv.y;
    o.z = acc.z * sc + bv.z;
    o.w = acc.w * sc + bv.w;
    if (RELU) {
        o.x = fmaxf(o.x, 0.f); o.y = fmaxf(o.y, 0.f);
        o.z = fmaxf(o.z, 0.f); o.w = fmaxf(o.w, 0.f);
    }
    ((float4*)out)[(size_t)warp * 32 + lane] = o;
}

__global__ void aggregate64_kernel(const __half* __restrict__ g,
                                   const float* __restrict__ bias,
                                   float* __restrict__ out, int n)
{
    int warp = (blockIdx.x * blockDim.x + threadIdx.x) >> 5;
    if (warp >= n) return;
    int lane = threadIdx.x & 31;

    const __half2* g2 = (const __half2*)g;
    float2 acc = __half22float2(g2[(size_t)warp * 32 + lane]);
    int e = g_off[warp];
    int end = g_off[warp + 1];
    while (e < end) {
        int m = min(32, end - e);
        int s = (lane < m) ? g_srcs[e + lane] : 0;
#pragma unroll 4
        for (int j = 0; j < m; j++) {
            int sj = __shfl_sync(0xffffffffu, s, j);
            float2 v = __half22float2(g2[(size_t)sj * 32 + lane]);
            acc.x += v.x; acc.y += v.y;
        }
        e += m;
    }
    float sc = g_dinv[warp];
    float2 bv = ((const float2*)bias)[lane];
    float2 o;
    o.x = acc.x * sc + bv.x;
    o.y = acc.y * sc + bv.y;
    ((float2*)out)[(size_t)warp * 32 + lane] = o;
}

// ---------------------------------------------------------------------------
extern "C" void kernel_launch(void* const* d_in, const int* in_sizes, int n_in,
                              void* d_out, int out_size) {
    const float* x  = (const float*)d_in[0];
    const void*  ei = d_in[1];
    const float* W1 = (const float*)d_in[2];
    const float* b1 = (const float*)d_in[3];
    const float* W2 = (const float*)d_in[4];
    const float* b2 = (const float*)d_in[5];
    const float* W3 = (const float*)d_in[6];
    const float* b3 = (const float*)d_in[7];
    float* out = (float*)d_out;

    const int n = in_sizes[0] / 128;   // 50000
    const int E = in_sizes[1] / 2;     // 800000

    __half* hh = nullptr;
    float* t = nullptr;
    cudaGetSymbolAddress((void**)&hh, g_hh);
    cudaGetSymbolAddress((void**)&t, g_t);

    const int smem128 = 128 * 144 * 2 + 128 * 144 * 2 + 8 * 16 * 24 * 4; // 86016
    const int smem64  = 128 * 80 * 2  + 128 * 144 * 2 + 8 * 16 * 24 * 4; // 69632
    cudaFuncSetAttribute(gemm_wmma_kernel<128>,
                         cudaFuncAttributeMaxDynamicSharedMemorySize, smem128);
    cudaFuncSetAttribute(gemm_wmma_kernel<64>,
                         cudaFuncAttributeMaxDynamicSharedMemorySize, smem64);

    // Side stream + events for capture-fork (created once; no device allocs).
    static cudaStream_t s1 = nullptr;
    static cudaEvent_t ev_scan = nullptr, ev_g1 = nullptr;
    if (s1 == nullptr) {
        cudaStreamCreateWithFlags(&s1, cudaStreamNonBlocking);
        cudaEventCreateWithFlags(&ev_scan, cudaEventDisableTiming);
        cudaEventCreateWithFlags(&ev_g1, cudaEventDisableTiming);
    }

    const int gemm_grid = 296;   // persistent, 2 CTAs/SM
    const int agg_blocks = (n * 32 + 255) / 256;
    const int e4_blocks = (E + 1023) / 1024;

    // ---- CSR build (main stream) ----
    init_detect_kernel<<<(n + 255) / 256, 256>>>(ei, E, n);
    hist_kernel<<<e4_blocks, 256>>>(ei, E);
    scan_fused_kernel<<<SCAN_GRID, SCAN_B>>>(n, E);

    // ---- fork: layer-1 GEMM (needs only x, W1, dinv) overlaps scatter ----
    cudaEventRecord(ev_scan, 0);
    cudaStreamWaitEvent(s1, ev_scan, 0);
    gemm_wmma_kernel<128><<<gemm_grid, 256, smem128, s1>>>(x, W1, hh, n);
    cudaEventRecord(ev_g1, s1);

    scatter_kernel<<<e4_blocks, 256>>>(ei, E);      // main stream, atomic-free
    cudaStreamWaitEvent(0, ev_g1, 0);               // join before aggregation

    // ---- layer 1 aggregation ----
    aggregate128_kernel<true><<<agg_blocks, 256>>>(hh, b1, t, n);
    // ---- layer 2 ----
    gemm_wmma_kernel<128><<<gemm_grid, 256, smem128>>>(t, W2, hh, n);
    aggregate128_kernel<true><<<agg_blocks, 256>>>(hh, b2, t, n);
    // ---- layer 3 ----
    gemm_wmma_kernel<64><<<gemm_grid, 256, smem64>>>(t, W3, hh, n);
    aggregate64_kernel<<<agg_blocks, 256>>>(hh, b3, out, n);
}

// round 14
// speedup vs baseline: 1.0844x; 1.0844x over previous
#include <cuda_runtime.h>
#include <cuda_fp16.h>
#include <mma.h>
#include <cstdint>
#include <type_traits>

// ---------------------------------------------------------------------------
// 3-layer GCN. Key structure this round:
//  - GEMM1 stores UNSCALED XW (fp16) and has zero CSR dependencies -> forked
//    at capture start, overlapping the whole CSR build (init+hist+scan+scatter).
//  - aggregate1 applies dinv[s] per edge (shuffled) and dinv[d] at the end.
//  - Aggregation outputs fp16 directly; GEMMs 2,3 take fp16 A (pure copy, no
//    convert) and keep the dinv epilogue scale.
// ---------------------------------------------------------------------------

#define MAXN 50000
#define MAXE 800000
#define SCAN_B 1024
#define SCAN_GRID ((MAXN + SCAN_B - 1) / SCAN_B)   // 49

__device__ __half g_hh[(size_t)MAXN * 128];  // GEMM output (fp16)
__device__ __half g_th[(size_t)MAXN * 128];  // aggregation output (fp16)
__device__ float  g_dinv[MAXN];
__device__ int    g_cnt[MAXN];
__device__ int    g_off[MAXN + 1];
__device__ int    g_rank[MAXE];
__device__ int    g_srcs[MAXE];
__device__ int    g_bflag[SCAN_GRID];
__device__ int    g_is64;

// ---------------------------------------------------------------------------
__global__ void init_detect_kernel(const void* edges, int E, int n) {
    int i = blockIdx.x * blockDim.x + threadIdx.x;
    if (i < n) g_cnt[i] = 0;
    if (i < SCAN_GRID) g_bflag[i] = 0;
    if (blockIdx.x == 0) {
        __shared__ int nz;
        if (threadIdx.x == 0) nz = 0;
        __syncthreads();
        const int* w = (const int*)edges;
        int cnt = 0;
        for (int k = threadIdx.x; k < 2048; k += blockDim.x) {
            int idx = 2 * k + 1;
            if (idx < 2 * E && w[idx] != 0) cnt++;
        }
        atomicAdd(&nz, cnt);
        __syncthreads();
        if (threadIdx.x == 0) g_is64 = (nz == 0) ? 1 : 0;
    }
}

__device__ __forceinline__ int edge_val(const void* p, long long idx) {
    if (g_is64) return (int)((const long long*)p)[idx];
    return ((const int*)p)[idx];
}

__global__ void hist_kernel(const void* edges, int E) {
    int base = blockIdx.x * (blockDim.x * 4) + threadIdx.x;
    int d[4], e_[4];
#pragma unroll
    for (int k = 0; k < 4; k++) {
        e_[k] = base + k * blockDim.x;
        d[k] = (e_[k] < E) ? edge_val(edges, (long long)E + e_[k]) : -1;
    }
#pragma unroll
    for (int k = 0; k < 4; k++)
        if (d[k] >= 0) g_rank[e_[k]] = atomicAdd(&g_cnt[d[k]], 1);
}

__global__ __launch_bounds__(SCAN_B) void scan_fused_kernel(int n, int E) {
    __shared__ int wsum[32];
    __shared__ int sums[SCAN_GRID];
    __shared__ int base_sh;
    const int b = blockIdx.x;
    int gid = b * SCAN_B + threadIdx.x;
    int lane = threadIdx.x & 31;
    int wid = threadIdx.x >> 5;

    int c = (gid < n) ? g_cnt[gid] : 0;
    if (gid < n) g_dinv[gid] = rsqrtf((float)(c + 1));

    int v = c;
#pragma unroll
    for (int o = 1; o < 32; o <<= 1) {
        int u = __shfl_up_sync(0xffffffffu, v, o);
        if (lane >= o) v += u;
    }
    if (lane == 31) wsum[wid] = v;
    __syncthreads();
    if (wid == 0) {
        int w = (lane < SCAN_B / 32) ? wsum[lane] : 0;
#pragma unroll
        for (int o = 1; o < 32; o <<= 1) {
            int u = __shfl_up_sync(0xffffffffu, w, o);
            if (lane >= o) w += u;
        }
        wsum[lane] = w;
    }
    __syncthreads();
    int wbase = (wid == 0) ? 0 : wsum[wid - 1];
    int excl = wbase + v - c;

    if (threadIdx.x == SCAN_B - 1)
        atomicExch(&g_bflag[b], wbase + v + 1);

    if (threadIdx.x < SCAN_GRID) {
        volatile int* f = g_bflag;
        int val;
        do { val = f[threadIdx.x]; } while (val == 0);
        sums[threadIdx.x] = val - 1;
    }
    __syncthreads();
    if (threadIdx.x == 0) {
        int base = 0;
        for (int j = 0; j < b; j++) base += sums[j];
        base_sh = base;
    }
    __syncthreads();

    if (gid < n) g_off[gid] = excl + base_sh;
    if (b == SCAN_GRID - 1 && threadIdx.x == SCAN_B - 1) g_off[n] = E;
}

__global__ void scatter_kernel(const void* edges, int E) {
    int base = blockIdx.x * (blockDim.x * 4) + threadIdx.x;
    int d[4], s[4], r[4], e_[4];
#pragma unroll
    for (int k = 0; k < 4; k++) {
        e_[k] = base + k * blockDim.x;
        if (e_[k] < E) {
            d[k] = edge_val(edges, (long long)E + e_[k]);
            s[k] = edge_val(edges, e_[k]);
            r[k] = g_rank[e_[k]];
        } else d[k] = -1;
    }
    int off[4];
#pragma unroll
    for (int k = 0; k < 4; k++)
        off[k] = (d[k] >= 0) ? g_off[d[k]] : 0;
#pragma unroll
    for (int k = 0; k < 4; k++)
        if (d[k] >= 0) g_srcs[off[k] + r[k]] = s[k];
}

// ---------------------------------------------------------------------------
// WMMA fp16 GEMM: Ch[M,N] = fp16( (A @ W) * (SCALE_ROW ? dinv[row] : 1) )
// TA=float: convert path (layer 1, A=x). TA=__half: pure copy path.
// ---------------------------------------------------------------------------
template <int N, bool SCALE_ROW, typename TA>
__global__ __launch_bounds__(256) void gemm_wmma_kernel(
    const TA* __restrict__ A, const float* __restrict__ W,
    __half* __restrict__ Ch, int M)
{
    using namespace nvcuda;
    constexpr int K = 128, BM = 128;
    constexpr int LDA = K + 16;
    constexpr int LDW = N + 16;
    constexpr int LDS_ = 24;
    constexpr int WMF = 2;
    constexpr int WNF = N / 32;

    extern __shared__ __align__(32) char smem[];
    __half* Wh = (__half*)smem;
    __half* Ah = (__half*)(smem + (size_t)K * LDW * 2);
    float* stage = (float*)(smem + (size_t)K * LDW * 2 + (size_t)BM * LDA * 2);

    const int tid = threadIdx.x;
    const int wid = tid >> 5;
    const int lane = tid & 31;
    const int warp_m = wid & 3;
    const int warp_n = wid >> 2;
    float* st = stage + wid * 16 * LDS_;

    for (int g = tid; g < K * N / 4; g += 256) {
        int k  = g / (N / 4);
        int c4 = (g % (N / 4)) * 4;
        float4 v = *(const float4*)&W[(size_t)k * N + c4];
        __half2 h01 = __floats2half2_rn(v.x, v.y);
        __half2 h23 = __floats2half2_rn(v.z, v.w);
        uint2 u = make_uint2(*(uint32_t*)&h01, *(uint32_t*)&h23);
        *(uint2*)&Wh[(size_t)k * LDW + c4] = u;
    }

    const int n_tiles = (M + BM - 1) / BM;
    for (int tile = blockIdx.x; tile < n_tiles; tile += gridDim.x) {
        const int brow = tile * BM;

        if constexpr (std::is_same<TA, float>::value) {
            for (int g = tid; g < BM * K / 4; g += 256) {
                int r  = g >> 5;
                int c4 = (g & 31) * 4;
                float4 v = make_float4(0.f, 0.f, 0.f, 0.f);
                if (brow + r < M)
                    v = *(const float4*)&A[(size_t)(brow + r) * K + c4];
                __half2 h01 = __floats2half2_rn(v.x, v.y);
                __half2 h23 = __floats2half2_rn(v.z, v.w);
                uint2 u = make_uint2(*(uint32_t*)&h01, *(uint32_t*)&h23);
                *(uint2*)&Ah[(size_t)r * LDA + c4] = u;
            }
        } else {
            // fp16 A: straight 16B copies, no convert
            for (int g = tid; g < BM * K / 8; g += 256) {
                int r  = g >> 4;
                int c8 = (g & 15) * 8;
                uint4 u = make_uint4(0, 0, 0, 0);
                if (brow + r < M)
                    u = *(const uint4*)&A[(size_t)(brow + r) * K + c8];
                *(uint4*)&Ah[(size_t)r * LDA + c8] = u;
            }
        }
        __syncthreads();

        wmma::fragment<wmma::accumulator, 16, 16, 16, float> cf[WMF][WNF];
#pragma unroll
        for (int i = 0; i < WMF; i++)
#pragma unroll
            for (int j = 0; j < WNF; j++)
                wmma::fill_fragment(cf[i][j], 0.f);

#pragma unroll
        for (int k = 0; k < K; k += 16) {
            wmma::fragment<wmma::matrix_a, 16, 16, 16, __half, wmma::row_major> af[WMF];
#pragma unroll
            for (int i = 0; i < WMF; i++)
                wmma::load_matrix_sync(af[i],
                    &Ah[(size_t)(warp_m * 32 + i * 16) * LDA + k], LDA);
#pragma unroll
            for (int j = 0; j < WNF; j++) {
                wmma::fragment<wmma::matrix_b, 16, 16, 16, __half, wmma::row_major> bf;
                wmma::load_matrix_sync(bf,
                    &Wh[(size_t)k * LDW + warp_n * WNF * 16 + j * 16], LDW);
#pragma unroll
                for (int i = 0; i < WMF; i++)
                    wmma::mma_sync(cf[i][j], af[i], bf, cf[i][j]);
            }
        }

#pragma unroll
        for (int i = 0; i < WMF; i++) {
#pragma unroll
            for (int j = 0; j < WNF; j++) {
                wmma::store_matrix_sync(st, cf[i][j], LDS_, wmma::mem_row_major);
                __syncwarp();
                int rloc = lane >> 1;
                int cg = (lane & 1) * 8;
                int r = brow + warp_m * 32 + i * 16 + rloc;
                if (r < M) {
                    float s = SCALE_ROW ? g_dinv[r] : 1.0f;
                    float4 va = *(float4*)&st[rloc * LDS_ + cg + 0];
                    float4 vb = *(float4*)&st[rloc * LDS_ + cg + 4];
                    __align__(16) __half2 hv[4];
                    hv[0] = __floats2half2_rn(va.x * s, va.y * s);
                    hv[1] = __floats2half2_rn(va.z * s, va.w * s);
                    hv[2] = __floats2half2_rn(vb.x * s, vb.y * s);
                    hv[3] = __floats2half2_rn(vb.z * s, vb.w * s);
                    __half* dst = &Ch[(size_t)r * N + warp_n * WNF * 16 + j * 16 + cg];
                    *(uint4*)dst = *(uint4*)hv;
                }
                __syncwarp();
            }
        }
        __syncthreads();
    }
}

// ---------------------------------------------------------------------------
// Warp-per-node aggregation: fp16 gathers, fp32 accumulate.
// SCALE_SRC: g is UNSCALED; multiply each gathered row by dinv[src].
// OutT: __half (feeds next GEMM) or float (final output).
// ---------------------------------------------------------------------------
__device__ __forceinline__ float4 gather4h(const __half* g, int row, int lane) {
    uint2 u = *(const uint2*)(g + (size_t)row * 128 + lane * 4);
    __half2 h0 = *(__half2*)&u.x;
    __half2 h1 = *(__half2*)&u.y;
    float2 f0 = __half22float2(h0);
    float2 f1 = __half22float2(h1);
    return make_float4(f0.x, f0.y, f1.x, f1.y);
}

template <bool RELU, bool SCALE_SRC, typename OutT>
__global__ void aggregate128_kernel(const __half* __restrict__ g,
                                    const float* __restrict__ bias,
                                    OutT* __restrict__ out, int n)
{
    int warp = (blockIdx.x * blockDim.x + threadIdx.x) >> 5;
    if (warp >= n) return;
    int lane = threadIdx.x & 31;
    float sc = g_dinv[warp];

    float4 acc = gather4h(g, warp, lane);   // self-loop term
    if (SCALE_SRC) { acc.x *= sc; acc.y *= sc; acc.z *= sc; acc.w *= sc; }

    int e = g_off[warp];
    int end = g_off[warp + 1];
    while (e < end) {
        int m = min(32, end - e);
        int s = (lane < m) ? g_srcs[e + lane] : 0;
        float dv = 0.f;
        if (SCALE_SRC) dv = (lane < m) ? g_dinv[s] : 0.f;
#pragma unroll 4
        for (int j = 0; j < m; j++) {
            int sj = __shfl_sync(0xffffffffu, s, j);
            float4 v = gather4h(g, sj, lane);
            if (SCALE_SRC) {
                float dj = __shfl_sync(0xffffffffu, dv, j);
                acc.x += dj * v.x; acc.y += dj * v.y;
                acc.z += dj * v.z; acc.w += dj * v.w;
            } else {
                acc.x += v.x; acc.y += v.y; acc.z += v.z; acc.w += v.w;
            }
        }
        e += m;
    }

    float4 bv = ((const float4*)bias)[lane];
    float4 o;
    o.x = acc.x * sc + bv.x;
    o.y = acc.y * sc + bv.y;
    o.z = acc.z * sc + bv.z;
    o.w = acc.w * sc + bv.w;
    if (RELU) {
        o.x = fmaxf(o.x, 0.f); o.y = fmaxf(o.y, 0.f);
        o.z = fmaxf(o.z, 0.f); o.w = fmaxf(o.w, 0.f);
    }
    if constexpr (std::is_same<OutT, __half>::value) {
        __half2 o01 = __floats2half2_rn(o.x, o.y);
        __half2 o23 = __floats2half2_rn(o.z, o.w);
        uint2 u = make_uint2(*(uint32_t*)&o01, *(uint32_t*)&o23);
        *(uint2*)(out + (size_t)warp * 128 + lane * 4) = u;
    } else {
        *(float4*)(out + (size_t)warp * 128 + lane * 4) = o;
    }
}

__global__ void aggregate64_kernel(const __half* __restrict__ g,
                                   const float* __restrict__ bias,
                                   float* __restrict__ out, int n)
{
    int warp = (blockIdx.x * blockDim.x + threadIdx.x) >> 5;
    if (warp >= n) return;
    int lane = threadIdx.x & 31;

    const __half2* g2 = (const __half2*)g;
    float2 acc = __half22float2(g2[(size_t)warp * 32 + lane]);
    int e = g_off[warp];
    int end = g_off[warp + 1];
    while (e < end) {
        int m = min(32, end - e);
        int s = (lane < m) ? g_srcs[e + lane] : 0;
#pragma unroll 4
        for (int j = 0; j < m; j++) {
            int sj = __shfl_sync(0xffffffffu, s, j);
            float2 v = __half22float2(g2[(size_t)sj * 32 + lane]);
            acc.x += v.x; acc.y += v.y;
        }
        e += m;
    }
    float sc = g_dinv[warp];
    float2 bv = ((const float2*)bias)[lane];
    float2 o;
    o.x = acc.x * sc + bv.x;
    o.y = acc.y * sc + bv.y;
    ((float2*)out)[(size_t)warp * 32 + lane] = o;
}

// ---------------------------------------------------------------------------
extern "C" void kernel_launch(void* const* d_in, const int* in_sizes, int n_in,
                              void* d_out, int out_size) {
    const float* x  = (const float*)d_in[0];
    const void*  ei = d_in[1];
    const float* W1 = (const float*)d_in[2];
    const float* b1 = (const float*)d_in[3];
    const float* W2 = (const float*)d_in[4];
    const float* b2 = (const float*)d_in[5];
    const float* W3 = (const float*)d_in[6];
    const float* b3 = (const float*)d_in[7];
    float* out = (float*)d_out;

    const int n = in_sizes[0] / 128;   // 50000
    const int E = in_sizes[1] / 2;     // 800000

    __half *hh = nullptr, *th = nullptr;
    cudaGetSymbolAddress((void**)&hh, g_hh);
    cudaGetSymbolAddress((void**)&th, g_th);

    const int smem128 = 128 * 144 * 2 + 128 * 144 * 2 + 8 * 16 * 24 * 4; // 86016
    const int smem64  = 128 * 80 * 2  + 128 * 144 * 2 + 8 * 16 * 24 * 4; // 69632
    cudaFuncSetAttribute((const void*)gemm_wmma_kernel<128, false, float>,
                         cudaFuncAttributeMaxDynamicSharedMemorySize, smem128);
    cudaFuncSetAttribute((const void*)gemm_wmma_kernel<128, true, __half>,
                         cudaFuncAttributeMaxDynamicSharedMemorySize, smem128);
    cudaFuncSetAttribute((const void*)gemm_wmma_kernel<64, true, __half>,
                         cudaFuncAttributeMaxDynamicSharedMemorySize, smem64);

    // Side stream + events (created once; no device allocs).
    static cudaStream_t s1 = nullptr;
    static cudaEvent_t ev0 = nullptr, ev_g1 = nullptr;
    if (s1 == nullptr) {
        cudaStreamCreateWithFlags(&s1, cudaStreamNonBlocking);
        cudaEventCreateWithFlags(&ev0, cudaEventDisableTiming);
        cudaEventCreateWithFlags(&ev_g1, cudaEventDisableTiming);
    }

    const int gemm_grid = 296;
    const int agg_blocks = (n * 32 + 255) / 256;
    const int e4_blocks = (E + 1023) / 1024;

    // ---- fork at start: GEMM1 (unscaled, no CSR deps) overlaps entire CSR ----
    cudaEventRecord(ev0, 0);
    cudaStreamWaitEvent(s1, ev0, 0);
    gemm_wmma_kernel<128, false, float><<<gemm_grid, 256, smem128, s1>>>(x, W1, hh, n);
    cudaEventRecord(ev_g1, s1);

    // ---- CSR build (main stream) ----
    init_detect_kernel<<<(n + 255) / 256, 256>>>(ei, E, n);
    hist_kernel<<<e4_blocks, 256>>>(ei, E);
    scan_fused_kernel<<<SCAN_GRID, SCAN_B>>>(n, E);
    scatter_kernel<<<e4_blocks, 256>>>(ei, E);

    cudaStreamWaitEvent(0, ev_g1, 0);   // join

    // ---- layer 1: aggregate applies dinv[s] and dinv[d] ----
    aggregate128_kernel<true, true, __half><<<agg_blocks, 256>>>(hh, b1, th, n);
    // ---- layer 2 ----
    gemm_wmma_kernel<128, true, __half><<<gemm_grid, 256, smem128>>>(th, W2, hh, n);
    aggregate128_kernel<true, false, __half><<<agg_blocks, 256>>>(hh, b2, th, n);
    // ---- layer 3 ----
    gemm_wmma_kernel<64, true, __half><<<gemm_grid, 256, smem64>>>(th, W3, hh, n);
    aggregate64_kernel<<<agg_blocks, 256>>>(hh, b3, out, n);
}